// round 10
// baseline (speedup 1.0000x reference)
#include <cuda_runtime.h>
#include <math.h>

#define BB 128
#define TT 512
#define DD 300
#define HH 300
#define NG 1200     // 4*H
#define NGRP 16     // groups of 8 batch rows
#define ROWSG 8
#define NTIL 19     // CTAs per group (16 units each: 19*16 = 304 >= 300)
#define UCTA 16
#define NCTAS (NGRP*NTIL)   // 304 = 152 SMs x occupancy 2 (exact wave-1 fit)
#define KCH 40      // logical k per chunk (8*40 = 320 >= 300)
#define KST 44      // smem stride per chunk (banks kc*12 mod 32 distinct)
#define KPADF (8*KST)  // 352 floats per staged h row

typedef unsigned long long u64;

// ---- packed f32x2 helpers (FFMA2: only reachable via PTX) ----
__device__ __forceinline__ u64 f2pack(float lo, float hi) {
    u64 d; asm("mov.b64 %0, {%1, %2};" : "=l"(d) : "f"(lo), "f"(hi)); return d;
}
__device__ __forceinline__ void f2unpack(u64 v, float& lo, float& hi) {
    asm("mov.b64 {%0, %1}, %2;" : "=f"(lo), "=f"(hi) : "l"(v));
}
__device__ __forceinline__ u64 f2fma(u64 a, u64 b, u64 c) {
    u64 d; asm("fma.rn.f32x2 %0, %1, %2, %3;" : "=l"(d) : "l"(a), "l"(b), "l"(c)); return d;
}
__device__ __forceinline__ u64 f2add(u64 a, u64 b) {
    u64 d; asm("add.rn.f32x2 %0, %1, %2;" : "=l"(d) : "l"(a), "l"(b)); return d;
}

// ---- device scratch ----
__device__ float g_h[2][BB*HH];          // double-buffered hidden state
__device__ float g_xz[(size_t)BB*TT*NG]; // precomputed x@Wx + b_lstm
__device__ int   g_flag[NGRP*32];        // per-CTA epoch flags (groups 128B apart)

// ---------------------------------------------------------------------------
__global__ void init_kernel() {
    int i = blockIdx.x * blockDim.x + threadIdx.x;
    if (i < BB*HH) {
        g_h[0][i] = 0.f;
        g_h[1][i] = 0.f;
    }
    if (i < NGRP*32) g_flag[i] = 0;
}

// ---------------------------------------------------------------------------
// precompute: g_xz[b][t][n] = embedding[ids[b][t]] @ W_lstm[0:300, n] + b_lstm[n]
// (unchanged from passing rounds 7-9)
// ---------------------------------------------------------------------------
__global__ __launch_bounds__(256) void precompute_kernel(
    const int*   __restrict__ ids,
    const int*   __restrict__ lengths,
    const float* __restrict__ emb,
    const float* __restrict__ W,
    const float* __restrict__ bl)
{
    const int b  = blockIdx.z;
    const int t0 = blockIdx.y * 128;
    const int n0 = blockIdx.x * 64;
    if (lengths[b] <= t0) return;

    __shared__ float As[16][128];
    __shared__ float Bs[16][64];
    __shared__ int   toks[128];

    const int tid = threadIdx.x;
    if (tid < 128) toks[tid] = ids[b*TT + t0 + tid];

    const int tx = tid & 15;
    const int ty = tid >> 4;
    u64 acc2[4][4];
    #pragma unroll
    for (int i = 0; i < 4; i++)
        #pragma unroll
        for (int j = 0; j < 4; j++) acc2[i][j] = 0ull;

    for (int k0 = 0; k0 < 300; k0 += 16) {
        __syncthreads();
        for (int l = tid; l < 512; l += 256) {
            int r  = l >> 2;
            int kq = l & 3;
            int k  = k0 + kq * 4;
            float4 v = make_float4(0.f, 0.f, 0.f, 0.f);
            if (k < 300) v = *(const float4*)(emb + (size_t)toks[r]*DD + k);
            As[kq*4+0][r] = v.x;
            As[kq*4+1][r] = v.y;
            As[kq*4+2][r] = v.z;
            As[kq*4+3][r] = v.w;
        }
        {
            int l  = tid;
            int kk = l >> 4;
            int q  = l & 15;
            int k  = k0 + kk;
            int n  = n0 + q * 4;
            float4 v = make_float4(0.f, 0.f, 0.f, 0.f);
            if (k < 300 && n < NG) v = *(const float4*)(W + (size_t)k*NG + n);
            *(float4*)&Bs[kk][q*4] = v;
        }
        __syncthreads();
        #pragma unroll
        for (int kk = 0; kk < 16; kk++) {
            float4 bv = *(const float4*)&Bs[kk][tx*4];
            u64 b0 = f2pack(bv.x, bv.x);
            u64 b1 = f2pack(bv.y, bv.y);
            u64 b2 = f2pack(bv.z, bv.z);
            u64 b3 = f2pack(bv.w, bv.w);
            const u64* a2 = (const u64*)&As[kk][ty*8];
            #pragma unroll
            for (int mp = 0; mp < 4; mp++) {
                u64 av = a2[mp];
                acc2[mp][0] = f2fma(av, b0, acc2[mp][0]);
                acc2[mp][1] = f2fma(av, b1, acc2[mp][1]);
                acc2[mp][2] = f2fma(av, b2, acc2[mp][2]);
                acc2[mp][3] = f2fma(av, b3, acc2[mp][3]);
            }
        }
    }

    const int n = n0 + tx * 4;
    if (n < NG) {
        float4 blv = *(const float4*)(bl + n);
        #pragma unroll
        for (int mp = 0; mp < 4; mp++) {
            float x0,x1,y0,y1,z0,z1,q0,q1;
            f2unpack(acc2[mp][0], x0, x1);
            f2unpack(acc2[mp][1], y0, y1);
            f2unpack(acc2[mp][2], z0, z1);
            f2unpack(acc2[mp][3], q0, q1);
            int t = t0 + ty*8 + 2*mp;
            float4 o0 = make_float4(x0+blv.x, y0+blv.y, z0+blv.z, q0+blv.w);
            float4 o1 = make_float4(x1+blv.x, y1+blv.y, z1+blv.z, q1+blv.w);
            *(float4*)(g_xz + ((size_t)b*TT + t  )*NG + n) = o0;
            *(float4*)(g_xz + ((size_t)b*TT + t+1)*NG + n) = o1;
        }
    }
}

// ---------------------------------------------------------------------------
// persistent recurrence kernel v6: one (group, 16-unit tile) per CTA,
// 2 CTAs per SM (grid 304 = 152 SMs x occ 2; __launch_bounds__(256,2) forces
// regs<=128 so occupancy 2 — and thus spin-barrier liveness — is guaranteed).
// The two co-resident CTAs belong to different groups: the HW scheduler
// interleaves their warps, hiding each other's release->detect->restage
// chain (4 warps/SMSP of independent work vs r9's 2).
// Matmul: warp wid owns units ua=u0+2*wid, ub=ua+1; lane = kc*4+gate;
//   W held in 40 u64 regs/thread (step-invariant).
// Barrier: per-group epoch flags (19 CTAs), release store + coalesced
//   acquire-poll, as validated in r8/r9.
// Buffer-parity invariant per 8-row group: retires at its maxlen; final
// state in g_h[maxlen&1].
// ---------------------------------------------------------------------------
__global__ __launch_bounds__(256, 2) void lstm_persistent(
    const float* __restrict__ W,
    const int*   __restrict__ lengths)
{
    __shared__ __align__(16) float hs[ROWSG*KPADF];   // 8 x 352
    __shared__ __align__(16) float zsm[ROWSG*64];     // 8 rows x (16 units * 4 gates)
    __shared__ int sl[ROWSG];

    const int tid  = threadIdx.x;
    const int wid  = tid >> 5;             // warp 0..7
    const int lane = tid & 31;
    const int kc   = lane >> 2;            // k-chunk 0..7
    const int gg   = lane & 3;             // gate

    const int gid   = blockIdx.x / NTIL;   // group 0..15
    const int ntile = blockIdx.x % NTIL;
    const int m0    = gid * ROWSG;
    const int u0    = ntile * UCTA;
    const int ua    = u0 + 2*wid;          // this thread's two units
    const int ub    = ua + 1;

    if (tid < ROWSG) sl[tid] = lengths[m0 + tid];

    // W -> registers: 2 units x 20 f32x2 per thread (step-invariant)
    u64 w2a[20], w2b[20];
    #pragma unroll
    for (int i = 0; i < 20; i++) {
        int k0 = kc*KCH + 2*i;
        int k1 = k0 + 1;
        float a_lo = (k0 < HH && ua < HH) ? W[(size_t)(HH + k0)*NG + gg*HH + ua] : 0.f;
        float a_hi = (k1 < HH && ua < HH) ? W[(size_t)(HH + k1)*NG + gg*HH + ua] : 0.f;
        float b_lo = (k0 < HH && ub < HH) ? W[(size_t)(HH + k0)*NG + gg*HH + ub] : 0.f;
        float b_hi = (k1 < HH && ub < HH) ? W[(size_t)(HH + k1)*NG + gg*HH + ub] : 0.f;
        w2a[i] = f2pack(a_lo, a_hi);
        w2b[i] = f2pack(b_lo, b_hi);
    }
    __syncthreads();

    int maxlen = 0;
    #pragma unroll
    for (int i = 0; i < ROWSG; i++) maxlen = max(maxlen, sl[i]);

    // epilogue mapping: 1 (row, unit) per thread, first 128 threads
    const bool e_has  = (tid < ROWSG*UCTA);
    const int  e_mm   = tid >> 4;
    const int  e_uu   = tid & 15;
    const int  e_u    = u0 + e_uu;
    const int  e_b    = m0 + (e_has ? e_mm : 0);
    const bool e_uval = e_has && (e_u < HH);
    const int  e_len  = e_has ? sl[e_mm] : 0;
    const int  e_hsoff = (e_has ? e_mm : 0)*KPADF + (e_u/KCH)*KST + (e_u % KCH);

    int* flagbase = &g_flag[gid*32];
    int* myflag   = flagbase + ntile;

    float c_reg = 0.f;   // cell state for (e_b, e_u)

    for (int t = 0; t < maxlen; t++) {
        const float* hread  = g_h[t & 1];
        float*       hwrite = g_h[(t & 1) ^ 1];
        const bool   act    = e_uval && (t < e_len);

        // prefetch xz (epilogue operands; latency hidden behind matmul)
        const float* xzp = g_xz + ((size_t)e_b*TT + t)*NG + (e_uval ? e_u : 0);
        float pf0 = act ? __ldcg(xzp + 0*HH) : 0.f;
        float pf1 = act ? __ldcg(xzp + 1*HH) : 0.f;
        float pf2 = act ? __ldcg(xzp + 2*HH) : 0.f;
        float pf3 = act ? __ldcg(xzp + 3*HH) : 0.f;

        // stage h tile: 8 rows x 320 (chunks of 40 at stride 44 words)
        #pragma unroll
        for (int s = 0; s < 3; s++) {
            int l = tid + s*256;            // 0..639
            if (l < ROWSG*80) {
                int m  = l / 80;
                int q  = l - m*80;
                int kk = q / 10;
                int ii = q - kk*10;
                int k  = kk*KCH + ii*4;
                float4 v = make_float4(0.f, 0.f, 0.f, 0.f);
                if (k < HH) v = __ldcg((const float4*)(hread + (size_t)(m0+m)*HH + k));
                *(float4*)&hs[m*KPADF + kk*KST + ii*4] = v;
            }
        }
        __syncthreads();

        // matmul: per row, 2 unit dot-products over this thread's k-chunk
        #pragma unroll 2
        for (int m = 0; m < ROWSG; m++) {
            const u64* h2 = (const u64*)(hs + m*KPADF + kc*KST);
            u64 A0 = 0ull, A1 = 0ull, B0 = 0ull, B1 = 0ull;
            #pragma unroll
            for (int i = 0; i < 20; i += 2) {
                u64 ha = h2[i];
                u64 hb = h2[i+1];
                A0 = f2fma(w2a[i],   ha, A0);
                A1 = f2fma(w2a[i+1], hb, A1);
                B0 = f2fma(w2b[i],   ha, B0);
                B1 = f2fma(w2b[i+1], hb, B1);
            }
            float al, ah, bl_, bh;
            f2unpack(f2add(A0, A1), al, ah);
            f2unpack(f2add(B0, B1), bl_, bh);
            float va = al + ah;
            float vb = bl_ + bh;
            #pragma unroll
            for (int o = 4; o <= 16; o <<= 1) {
                va += __shfl_xor_sync(0xffffffffu, va, o);
                vb += __shfl_xor_sync(0xffffffffu, vb, o);
            }
            if (kc == 0) {
                zsm[m*64 + (2*wid + 0)*4 + gg] = va;
                zsm[m*64 + (2*wid + 1)*4 + gg] = vb;
            }
        }
        __syncthreads();

        // epilogue: one (row, unit) per thread
        if (act) {
            float4 zv = *(const float4*)&zsm[e_mm*64 + e_uu*4];
            float zi = zv.x + pf0;
            float zj = zv.y + pf1;
            float zf = zv.z + pf2;
            float zo = zv.w + pf3;
            float si = 1.f / (1.f + __expf(-zi));
            float sf = 1.f / (1.f + __expf(-(zf + 1.f)));  // FORGET_BIAS=1
            float so = 1.f / (1.f + __expf(-zo));
            float tj = tanhf(zj);
            c_reg = c_reg * sf + si * tj;
            float hnew = tanhf(c_reg) * so;
            __stcg(&hwrite[e_b*HH + e_u], hnew);
        } else if (e_uval) {
            __stcg(&hwrite[e_b*HH + e_u], hs[e_hsoff]);   // carry frozen state
        }

        // group barrier: release -> flags -> acquire-poll
        __syncthreads();
        if (tid == 0) {
            asm volatile("st.release.gpu.s32 [%0], %1;"
                         :: "l"(myflag), "r"(t + 1) : "memory");
        }
        if (tid < 32) {
            const bool has = (lane < NTIL);
            int* pp = flagbase + (has ? lane : 0);
            const int target = t + 1;
            int v;
            do {
                asm volatile("ld.acquire.gpu.s32 %0, [%1];"
                             : "=r"(v) : "l"(pp) : "memory");
            } while (!__all_sync(0xffffffffu, !has || (v >= target)));
        }
        __syncthreads();
    }
}

// ---------------------------------------------------------------------------
// final: logits + mean NLL. Row b's final h is in buffer (group maxlen & 1),
// group = b's 8-row block.
// ---------------------------------------------------------------------------
__global__ void final_kernel(
    const float* __restrict__ Wd,
    const float* __restrict__ bd,
    const int*   __restrict__ labels,
    const int*   __restrict__ lengths,
    float*       __restrict__ out,
    int out_size)
{
    __shared__ float red[128];
    __shared__ int   slen[128];
    __shared__ float wd_s[900];
    int b = threadIdx.x;
    slen[b] = lengths[b];
    for (int i = b; i < 900; i += 128) wd_s[i] = Wd[i];
    __syncthreads();

    int tile0 = b & ~(ROWSG - 1);
    int maxlen = 0;
    #pragma unroll
    for (int i = 0; i < ROWSG; i++) maxlen = max(maxlen, slen[tile0 + i]);
    const float* h = g_h[maxlen & 1] + b*HH;

    float a0 = bd[0], a1 = bd[1], a2 = bd[2];
    #pragma unroll 5
    for (int k = 0; k < HH; k += 4) {
        float4 hv = *(const float4*)(h + k);
        a0 += hv.x*wd_s[(k+0)*3+0] + hv.y*wd_s[(k+1)*3+0]
            + hv.z*wd_s[(k+2)*3+0] + hv.w*wd_s[(k+3)*3+0];
        a1 += hv.x*wd_s[(k+0)*3+1] + hv.y*wd_s[(k+1)*3+1]
            + hv.z*wd_s[(k+2)*3+1] + hv.w*wd_s[(k+3)*3+1];
        a2 += hv.x*wd_s[(k+0)*3+2] + hv.y*wd_s[(k+1)*3+2]
            + hv.z*wd_s[(k+2)*3+2] + hv.w*wd_s[(k+3)*3+2];
    }
    float mx  = fmaxf(a0, fmaxf(a1, a2));
    float lse = mx + logf(expf(a0 - mx) + expf(a1 - mx) + expf(a2 - mx));
    int   lab = labels[b];
    float sel = (lab == 0) ? a0 : ((lab == 1) ? a1 : a2);
    float nll = lse - sel;

    int off = (out_size >= 385) ? 1 : 0;
    if (out_size >= 384) {
        out[off + b*3 + 0] = a0;
        out[off + b*3 + 1] = a1;
        out[off + b*3 + 2] = a2;
    }
    red[b] = nll;
    __syncthreads();
    for (int s = 64; s; s >>= 1) {
        if (b < s) red[b] += red[b + s];
        __syncthreads();
    }
    if (b == 0 && (off == 1 || out_size < 384)) out[0] = red[0] * (1.f / 128.f);
}

// ---------------------------------------------------------------------------
extern "C" void kernel_launch(void* const* d_in, const int* in_sizes, int n_in,
                              void* d_out, int out_size)
{
    const int*   ids     = (const int*)  d_in[0];
    const int*   lengths = (const int*)  d_in[1];
    const int*   labels  = (const int*)  d_in[2];
    const float* emb     = (const float*)d_in[3];
    const float* W       = (const float*)d_in[4];
    const float* bl      = (const float*)d_in[5];
    const float* Wd      = (const float*)d_in[6];
    const float* bd      = (const float*)d_in[7];
    float* out = (float*)d_out;

    init_kernel<<<(BB*HH + 255)/256, 256>>>();
    precompute_kernel<<<dim3(19, 4, BB), 256>>>(ids, lengths, emb, W, bl);
    lstm_persistent<<<NCTAS, 256>>>(W, lengths);
    final_kernel<<<1, 128>>>(Wd, bd, labels, lengths, out, out_size);
}

// round 11
// speedup vs baseline: 1.0528x; 1.0528x over previous
#include <cuda_runtime.h>
#include <math.h>

#define BB 128
#define TT 512
#define DD 300
#define HH 300
#define NG 1200     // 4*H
#define NGRP 16     // groups of 8 batch rows (length-sorted)
#define ROWSG 8
#define NTIL 19     // CTAs per group (16 units each: 19*16 = 304 >= 300)
#define UCTA 16
#define NBLK 8      // CTA blocks; block j hosts groups j (half0) and 15-j (half1)
#define NCTAS (NBLK*NTIL)   // 152 == GB300 SM count, 1 CTA/SM
#define KCH 40      // logical k per chunk (8*40 = 320 >= 300)
#define KST 44      // smem stride per chunk (banks kc*12 mod 32 distinct)
#define KPADF (8*KST)  // 352 floats per staged h row

typedef unsigned long long u64;

// ---- packed f32x2 helpers (FFMA2: only reachable via PTX) ----
__device__ __forceinline__ u64 f2pack(float lo, float hi) {
    u64 d; asm("mov.b64 %0, {%1, %2};" : "=l"(d) : "f"(lo), "f"(hi)); return d;
}
__device__ __forceinline__ void f2unpack(u64 v, float& lo, float& hi) {
    asm("mov.b64 {%0, %1}, %2;" : "=f"(lo), "=f"(hi) : "l"(v));
}
__device__ __forceinline__ u64 f2fma(u64 a, u64 b, u64 c) {
    u64 d; asm("fma.rn.f32x2 %0, %1, %2, %3;" : "=l"(d) : "l"(a), "l"(b), "l"(c)); return d;
}
__device__ __forceinline__ u64 f2add(u64 a, u64 b) {
    u64 d; asm("add.rn.f32x2 %0, %1, %2;" : "=l"(d) : "l"(a), "l"(b)); return d;
}

// half-CTA barrier (ids 1 and 2; 256 threads each)
__device__ __forceinline__ void barh(int half) {
    asm volatile("bar.sync %0, 256;" :: "r"(half + 1) : "memory");
}

// ---- device scratch ----
__device__ float g_h[2][BB*HH];          // double-buffered hidden state
__device__ float g_xz[(size_t)BB*TT*NG]; // precomputed x@Wx + b_lstm
__device__ int   g_flag[NGRP*32];        // per-CTA epoch flags (groups 128B apart)
__device__ int   g_perm[BB];             // rows sorted by length descending

// ---------------------------------------------------------------------------
// init: zero h buffers + flags; block 0 also rank-sorts rows by length
// (descending, stable) into g_perm.
// ---------------------------------------------------------------------------
__global__ void init_kernel(const int* __restrict__ lengths) {
    int i = blockIdx.x * blockDim.x + threadIdx.x;
    if (i < BB*HH) {
        g_h[0][i] = 0.f;
        g_h[1][i] = 0.f;
    }
    if (i < NGRP*32) g_flag[i] = 0;

    __shared__ int sle[BB];
    if (blockIdx.x == 0) {
        if (threadIdx.x < BB) sle[threadIdx.x] = lengths[threadIdx.x];
        __syncthreads();
        if (threadIdx.x < BB) {
            int t  = threadIdx.x;
            int me = sle[t];
            int rank = 0;
            for (int j = 0; j < BB; j++)
                rank += (sle[j] > me) || (sle[j] == me && j < t);
            g_perm[rank] = t;
        }
    }
}

// ---------------------------------------------------------------------------
// precompute: g_xz[b][t][n] = embedding[ids[b][t]] @ W_lstm[0:300, n] + b_lstm[n]
// (unchanged from passing rounds 7-10)
// ---------------------------------------------------------------------------
__global__ __launch_bounds__(256) void precompute_kernel(
    const int*   __restrict__ ids,
    const int*   __restrict__ lengths,
    const float* __restrict__ emb,
    const float* __restrict__ W,
    const float* __restrict__ bl)
{
    const int b  = blockIdx.z;
    const int t0 = blockIdx.y * 128;
    const int n0 = blockIdx.x * 64;
    if (lengths[b] <= t0) return;

    __shared__ float As[16][128];
    __shared__ float Bs[16][64];
    __shared__ int   toks[128];

    const int tid = threadIdx.x;
    if (tid < 128) toks[tid] = ids[b*TT + t0 + tid];

    const int tx = tid & 15;
    const int ty = tid >> 4;
    u64 acc2[4][4];
    #pragma unroll
    for (int i = 0; i < 4; i++)
        #pragma unroll
        for (int j = 0; j < 4; j++) acc2[i][j] = 0ull;

    for (int k0 = 0; k0 < 300; k0 += 16) {
        __syncthreads();
        for (int l = tid; l < 512; l += 256) {
            int r  = l >> 2;
            int kq = l & 3;
            int k  = k0 + kq * 4;
            float4 v = make_float4(0.f, 0.f, 0.f, 0.f);
            if (k < 300) v = *(const float4*)(emb + (size_t)toks[r]*DD + k);
            As[kq*4+0][r] = v.x;
            As[kq*4+1][r] = v.y;
            As[kq*4+2][r] = v.z;
            As[kq*4+3][r] = v.w;
        }
        {
            int l  = tid;
            int kk = l >> 4;
            int q  = l & 15;
            int k  = k0 + kk;
            int n  = n0 + q * 4;
            float4 v = make_float4(0.f, 0.f, 0.f, 0.f);
            if (k < 300 && n < NG) v = *(const float4*)(W + (size_t)k*NG + n);
            *(float4*)&Bs[kk][q*4] = v;
        }
        __syncthreads();
        #pragma unroll
        for (int kk = 0; kk < 16; kk++) {
            float4 bv = *(const float4*)&Bs[kk][tx*4];
            u64 b0 = f2pack(bv.x, bv.x);
            u64 b1 = f2pack(bv.y, bv.y);
            u64 b2 = f2pack(bv.z, bv.z);
            u64 b3 = f2pack(bv.w, bv.w);
            const u64* a2 = (const u64*)&As[kk][ty*8];
            #pragma unroll
            for (int mp = 0; mp < 4; mp++) {
                u64 av = a2[mp];
                acc2[mp][0] = f2fma(av, b0, acc2[mp][0]);
                acc2[mp][1] = f2fma(av, b1, acc2[mp][1]);
                acc2[mp][2] = f2fma(av, b2, acc2[mp][2]);
                acc2[mp][3] = f2fma(av, b3, acc2[mp][3]);
            }
        }
    }

    const int n = n0 + tx * 4;
    if (n < NG) {
        float4 blv = *(const float4*)(bl + n);
        #pragma unroll
        for (int mp = 0; mp < 4; mp++) {
            float x0,x1,y0,y1,z0,z1,q0,q1;
            f2unpack(acc2[mp][0], x0, x1);
            f2unpack(acc2[mp][1], y0, y1);
            f2unpack(acc2[mp][2], z0, z1);
            f2unpack(acc2[mp][3], q0, q1);
            int t = t0 + ty*8 + 2*mp;
            float4 o0 = make_float4(x0+blv.x, y0+blv.y, z0+blv.z, q0+blv.w);
            float4 o1 = make_float4(x1+blv.x, y1+blv.y, z1+blv.z, q1+blv.w);
            *(float4*)(g_xz + ((size_t)b*TT + t  )*NG + n) = o0;
            *(float4*)(g_xz + ((size_t)b*TT + t+1)*NG + n) = o1;
        }
    }
}

// ---------------------------------------------------------------------------
// persistent recurrence kernel v7: dual-group CTA with LENGTH-SORTED groups.
// grid = 152 CTAs (1/SM) x 512 threads. Block j: half0 (threads 0-255) runs
// group j (long), half1 runs group 15-j (short). Groups are 8 rows of the
// descending length-sorted permutation -> antipodal pairing balances per-SM
// work; the short half retires early and the long half gets the whole SM.
// Within a group rows are descending by length -> active rows at step t are
// the prefix [0, nact); frozen rows are skipped ENTIRELY (no carry: row b's
// final h lives in buffer lengths[b]&1, which final_kernel reads directly).
// Per half: warp w (0..7) owns units ua=u0+2w, ub=ua+1; lane = kc*4+gate;
// W in 40 u64 regs. Flag barrier per group (19 CTAs) as in r8-r10.
// ---------------------------------------------------------------------------
__global__ __launch_bounds__(512, 1) void lstm_persistent(
    const float* __restrict__ W,
    const int*   __restrict__ lengths)
{
    __shared__ __align__(16) float hs2[2][ROWSG*KPADF];
    __shared__ __align__(16) float zs2[2][ROWSG*64];
    __shared__ int prow2[2][ROWSG];
    __shared__ int sl2[2][ROWSG];

    const int tid  = threadIdx.x;
    const int half = tid >> 8;
    const int t256 = tid & 255;
    const int wid  = t256 >> 5;            // warp within half (0..7)
    const int lane = tid & 31;
    const int kc   = lane >> 2;            // k-chunk 0..7
    const int gg   = lane & 3;             // gate

    const int jblk  = blockIdx.x / NTIL;
    const int ntile = blockIdx.x % NTIL;
    const int gid   = half ? (NGRP - 1 - jblk) : jblk;
    const int u0    = ntile * UCTA;
    const int ua    = u0 + 2*wid;
    const int ub    = ua + 1;

    if (t256 < ROWSG) {
        int pr = g_perm[gid*ROWSG + t256];
        prow2[half][t256] = pr;
        sl2[half][t256]   = lengths[pr];
    }

    // W -> registers: 2 units x 20 f32x2 per thread (step-invariant)
    u64 w2a[20], w2b[20];
    #pragma unroll
    for (int i = 0; i < 20; i++) {
        int k0 = kc*KCH + 2*i;
        int k1 = k0 + 1;
        float a_lo = (k0 < HH && ua < HH) ? W[(size_t)(HH + k0)*NG + gg*HH + ua] : 0.f;
        float a_hi = (k1 < HH && ua < HH) ? W[(size_t)(HH + k1)*NG + gg*HH + ua] : 0.f;
        float b_lo = (k0 < HH && ub < HH) ? W[(size_t)(HH + k0)*NG + gg*HH + ub] : 0.f;
        float b_hi = (k1 < HH && ub < HH) ? W[(size_t)(HH + k1)*NG + gg*HH + ub] : 0.f;
        w2a[i] = f2pack(a_lo, a_hi);
        w2b[i] = f2pack(b_lo, b_hi);
    }
    __syncthreads();   // last whole-CTA sync (halves diverge after this)

    int sl[ROWSG];
    #pragma unroll
    for (int i = 0; i < ROWSG; i++) sl[i] = sl2[half][i];
    const int maxlen = sl[0];              // rows descending within group

    // epilogue mapping: first 128 threads of the half own one (row, unit)
    const bool e_has  = (t256 < ROWSG*UCTA);
    const int  e_mm   = (t256 >> 4) & 7;
    const int  e_uu   = t256 & 15;
    const int  e_u    = u0 + e_uu;
    const bool e_uval = e_has && (e_u < HH);
    const int  e_b    = prow2[half][e_mm];
    const int  e_len  = e_has ? sl[e_mm] : 0;

    float* hsh = hs2[half];
    float* zsh = zs2[half];
    int*   prw = prow2[half];
    int*   flagbase = &g_flag[gid*32];
    int*   myflag   = flagbase + ntile;

    float c_reg = 0.f;   // cell state for (e_b, e_u)

    for (int t = 0; t < maxlen; t++) {
        const float* hread  = g_h[t & 1];
        float*       hwrite = g_h[(t & 1) ^ 1];
        const bool   act    = e_uval && (t < e_len);

        // active prefix (uniform across half: sl identical in all its threads)
        int nact = 0;
        #pragma unroll
        for (int i = 0; i < ROWSG; i++) nact += (sl[i] > t);

        // prefetch xz (epilogue operands; latency hidden behind staging+matmul)
        const float* xzp = g_xz + ((size_t)e_b*TT + t)*NG + (e_uval ? e_u : 0);
        float pf0 = act ? __ldcg(xzp + 0*HH) : 0.f;
        float pf1 = act ? __ldcg(xzp + 1*HH) : 0.f;
        float pf2 = act ? __ldcg(xzp + 2*HH) : 0.f;
        float pf3 = act ? __ldcg(xzp + 3*HH) : 0.f;

        // stage ACTIVE h rows only: nact rows x 320 (chunks of 40, stride 44)
        {
            const int lim = nact * 80;
            #pragma unroll
            for (int s = 0; s < 3; s++) {
                int l = t256 + s*256;
                if (l < lim) {
                    int m  = l / 80;
                    int q  = l - m*80;
                    int kk = q / 10;
                    int ii = q - kk*10;
                    int k  = kk*KCH + ii*4;
                    float4 v = make_float4(0.f, 0.f, 0.f, 0.f);
                    if (k < HH)
                        v = __ldcg((const float4*)(hread + (size_t)prw[m]*HH + k));
                    *(float4*)&hsh[m*KPADF + kk*KST + ii*4] = v;
                }
            }
        }
        barh(half);

        // matmul over active rows: 2 unit dot-products per thread per row
        for (int m = 0; m < nact; m++) {
            const u64* h2 = (const u64*)(hsh + m*KPADF + kc*KST);
            u64 A0 = 0ull, A1 = 0ull, B0 = 0ull, B1 = 0ull;
            #pragma unroll
            for (int i = 0; i < 20; i += 2) {
                u64 ha = h2[i];
                u64 hb = h2[i+1];
                A0 = f2fma(w2a[i],   ha, A0);
                A1 = f2fma(w2a[i+1], hb, A1);
                B0 = f2fma(w2b[i],   ha, B0);
                B1 = f2fma(w2b[i+1], hb, B1);
            }
            float al, ah, bl_, bh;
            f2unpack(f2add(A0, A1), al, ah);
            f2unpack(f2add(B0, B1), bl_, bh);
            float va = al + ah;
            float vb = bl_ + bh;
            #pragma unroll
            for (int o = 4; o <= 16; o <<= 1) {
                va += __shfl_xor_sync(0xffffffffu, va, o);
                vb += __shfl_xor_sync(0xffffffffu, vb, o);
            }
            if (kc == 0) {
                zsh[m*64 + (2*wid + 0)*4 + gg] = va;
                zsh[m*64 + (2*wid + 1)*4 + gg] = vb;
            }
        }
        barh(half);

        // epilogue: one (row, unit) per thread; NO frozen-row carry
        if (act) {
            float4 zv = *(const float4*)&zsh[e_mm*64 + e_uu*4];
            float zi = zv.x + pf0;
            float zj = zv.y + pf1;
            float zf = zv.z + pf2;
            float zo = zv.w + pf3;
            float si = 1.f / (1.f + __expf(-zi));
            float sf = 1.f / (1.f + __expf(-(zf + 1.f)));  // FORGET_BIAS=1
            float so = 1.f / (1.f + __expf(-zo));
            float tj = tanhf(zj);
            c_reg = c_reg * sf + si * tj;
            float hnew = tanhf(c_reg) * so;
            __stcg(&hwrite[e_b*HH + e_u], hnew);
        }

        // group barrier: release -> flags -> acquire-poll
        barh(half);
        if (t256 == 0) {
            asm volatile("st.release.gpu.s32 [%0], %1;"
                         :: "l"(myflag), "r"(t + 1) : "memory");
        }
        if (t256 < 32) {
            const bool has = (lane < NTIL);
            int* pp = flagbase + (has ? lane : 0);
            const int target = t + 1;
            int v;
            do {
                asm volatile("ld.acquire.gpu.s32 %0, [%1];"
                             : "=r"(v) : "l"(pp) : "memory");
            } while (!__all_sync(0xffffffffu, !has || (v >= target)));
        }
        barh(half);
    }
}

// ---------------------------------------------------------------------------
// final: logits + mean NLL. Row b's final h lives in buffer (lengths[b] & 1):
// its last write was at t = len-1 into buffer ((len-1)&1)^1 = len&1.
// ---------------------------------------------------------------------------
__global__ void final_kernel(
    const float* __restrict__ Wd,
    const float* __restrict__ bd,
    const int*   __restrict__ labels,
    const int*   __restrict__ lengths,
    float*       __restrict__ out,
    int out_size)
{
    __shared__ float red[128];
    __shared__ float wd_s[900];
    int b = threadIdx.x;
    for (int i = b; i < 900; i += 128) wd_s[i] = Wd[i];
    __syncthreads();

    const float* h = g_h[lengths[b] & 1] + b*HH;

    float a0 = bd[0], a1 = bd[1], a2 = bd[2];
    #pragma unroll 5
    for (int k = 0; k < HH; k += 4) {
        float4 hv = *(const float4*)(h + k);
        a0 += hv.x*wd_s[(k+0)*3+0] + hv.y*wd_s[(k+1)*3+0]
            + hv.z*wd_s[(k+2)*3+0] + hv.w*wd_s[(k+3)*3+0];
        a1 += hv.x*wd_s[(k+0)*3+1] + hv.y*wd_s[(k+1)*3+1]
            + hv.z*wd_s[(k+2)*3+1] + hv.w*wd_s[(k+3)*3+1];
        a2 += hv.x*wd_s[(k+0)*3+2] + hv.y*wd_s[(k+1)*3+2]
            + hv.z*wd_s[(k+2)*3+2] + hv.w*wd_s[(k+3)*3+2];
    }
    float mx  = fmaxf(a0, fmaxf(a1, a2));
    float lse = mx + logf(expf(a0 - mx) + expf(a1 - mx) + expf(a2 - mx));
    int   lab = labels[b];
    float sel = (lab == 0) ? a0 : ((lab == 1) ? a1 : a2);
    float nll = lse - sel;

    int off = (out_size >= 385) ? 1 : 0;
    if (out_size >= 384) {
        out[off + b*3 + 0] = a0;
        out[off + b*3 + 1] = a1;
        out[off + b*3 + 2] = a2;
    }
    red[b] = nll;
    __syncthreads();
    for (int s = 64; s; s >>= 1) {
        if (b < s) red[b] += red[b + s];
        __syncthreads();
    }
    if (b == 0 && (off == 1 || out_size < 384)) out[0] = red[0] * (1.f / 128.f);
}

// ---------------------------------------------------------------------------
extern "C" void kernel_launch(void* const* d_in, const int* in_sizes, int n_in,
                              void* d_out, int out_size)
{
    const int*   ids     = (const int*)  d_in[0];
    const int*   lengths = (const int*)  d_in[1];
    const int*   labels  = (const int*)  d_in[2];
    const float* emb     = (const float*)d_in[3];
    const float* W       = (const float*)d_in[4];
    const float* bl      = (const float*)d_in[5];
    const float* Wd      = (const float*)d_in[6];
    const float* bd      = (const float*)d_in[7];
    float* out = (float*)d_out;

    init_kernel<<<(BB*HH + 255)/256, 256>>>(lengths);
    precompute_kernel<<<dim3(19, 4, BB), 256>>>(ids, lengths, emb, W, bl);
    lstm_persistent<<<NCTAS, 512>>>(W, lengths);
    final_kernel<<<1, 128>>>(Wd, bd, labels, lengths, out, out_size);
}

// round 12
// speedup vs baseline: 1.1527x; 1.0949x over previous
#include <cuda_runtime.h>
#include <math.h>

#define BB 128
#define TT 512
#define DD 300
#define HH 300
#define NG 1200     // 4*H
#define NGRP 16     // groups of 8 batch rows (length-sorted)
#define ROWSG 8
#define NTIL 19     // CTAs per group (16 units each: 19*16 = 304 >= 300)
#define UCTA 16
#define NBLK 8      // CTA blocks; block j hosts groups j (half0) and 15-j (half1)
#define NCTAS (NBLK*NTIL)   // 152 == GB300 SM count, 1 CTA/SM
#define KCH 40      // logical k per chunk (8*40 = 320 >= 300)
#define KST 44      // smem stride per chunk (banks kc*12 mod 32 distinct)
#define KPADF (8*KST)  // 352 floats per staged h row

typedef unsigned long long u64;

// ---- packed f32x2 helpers (FFMA2: only reachable via PTX) ----
__device__ __forceinline__ u64 f2pack(float lo, float hi) {
    u64 d; asm("mov.b64 %0, {%1, %2};" : "=l"(d) : "f"(lo), "f"(hi)); return d;
}
__device__ __forceinline__ void f2unpack(u64 v, float& lo, float& hi) {
    asm("mov.b64 {%0, %1}, %2;" : "=f"(lo), "=f"(hi) : "l"(v));
}
__device__ __forceinline__ u64 f2fma(u64 a, u64 b, u64 c) {
    u64 d; asm("fma.rn.f32x2 %0, %1, %2, %3;" : "=l"(d) : "l"(a), "l"(b), "l"(c)); return d;
}
__device__ __forceinline__ u64 f2add(u64 a, u64 b) {
    u64 d; asm("add.rn.f32x2 %0, %1, %2;" : "=l"(d) : "l"(a), "l"(b)); return d;
}

// half-CTA barrier (ids 1 and 2; 256 threads each)
__device__ __forceinline__ void barh(int half) {
    asm volatile("bar.sync %0, 256;" :: "r"(half + 1) : "memory");
}

// ---- device scratch ----
__device__ float g_h[2][BB*HH];          // double-buffered hidden state
__device__ float g_xz[(size_t)BB*TT*NG]; // precomputed x@Wx + b_lstm
__device__ int   g_flag[NGRP*32];        // per-CTA epoch flags (groups 128B apart)
__device__ int   g_perm[BB];             // rows sorted by length descending

// ---------------------------------------------------------------------------
// init: zero h buffers + flags; block 0 also rank-sorts rows by length
// (descending, stable) into g_perm.
// ---------------------------------------------------------------------------
__global__ void init_kernel(const int* __restrict__ lengths) {
    int i = blockIdx.x * blockDim.x + threadIdx.x;
    if (i < BB*HH) {
        g_h[0][i] = 0.f;
        g_h[1][i] = 0.f;
    }
    if (i < NGRP*32) g_flag[i] = 0;

    __shared__ int sle[BB];
    if (blockIdx.x == 0) {
        if (threadIdx.x < BB) sle[threadIdx.x] = lengths[threadIdx.x];
        __syncthreads();
        if (threadIdx.x < BB) {
            int t  = threadIdx.x;
            int me = sle[t];
            int rank = 0;
            for (int j = 0; j < BB; j++)
                rank += (sle[j] > me) || (sle[j] == me && j < t);
            g_perm[rank] = t;
        }
    }
}

// ---------------------------------------------------------------------------
// precompute: g_xz[b][t][n] = embedding[ids[b][t]] @ W_lstm[0:300, n] + b_lstm[n]
// (unchanged from passing rounds 7-10)
// ---------------------------------------------------------------------------
__global__ __launch_bounds__(256) void precompute_kernel(
    const int*   __restrict__ ids,
    const int*   __restrict__ lengths,
    const float* __restrict__ emb,
    const float* __restrict__ W,
    const float* __restrict__ bl)
{
    const int b  = blockIdx.z;
    const int t0 = blockIdx.y * 128;
    const int n0 = blockIdx.x * 64;
    if (lengths[b] <= t0) return;

    __shared__ float As[16][128];
    __shared__ float Bs[16][64];
    __shared__ int   toks[128];

    const int tid = threadIdx.x;
    if (tid < 128) toks[tid] = ids[b*TT + t0 + tid];

    const int tx = tid & 15;
    const int ty = tid >> 4;
    u64 acc2[4][4];
    #pragma unroll
    for (int i = 0; i < 4; i++)
        #pragma unroll
        for (int j = 0; j < 4; j++) acc2[i][j] = 0ull;

    for (int k0 = 0; k0 < 300; k0 += 16) {
        __syncthreads();
        for (int l = tid; l < 512; l += 256) {
            int r  = l >> 2;
            int kq = l & 3;
            int k  = k0 + kq * 4;
            float4 v = make_float4(0.f, 0.f, 0.f, 0.f);
            if (k < 300) v = *(const float4*)(emb + (size_t)toks[r]*DD + k);
            As[kq*4+0][r] = v.x;
            As[kq*4+1][r] = v.y;
            As[kq*4+2][r] = v.z;
            As[kq*4+3][r] = v.w;
        }
        {
            int l  = tid;
            int kk = l >> 4;
            int q  = l & 15;
            int k  = k0 + kk;
            int n  = n0 + q * 4;
            float4 v = make_float4(0.f, 0.f, 0.f, 0.f);
            if (k < 300 && n < NG) v = *(const float4*)(W + (size_t)k*NG + n);
            *(float4*)&Bs[kk][q*4] = v;
        }
        __syncthreads();
        #pragma unroll
        for (int kk = 0; kk < 16; kk++) {
            float4 bv = *(const float4*)&Bs[kk][tx*4];
            u64 b0 = f2pack(bv.x, bv.x);
            u64 b1 = f2pack(bv.y, bv.y);
            u64 b2 = f2pack(bv.z, bv.z);
            u64 b3 = f2pack(bv.w, bv.w);
            const u64* a2 = (const u64*)&As[kk][ty*8];
            #pragma unroll
            for (int mp = 0; mp < 4; mp++) {
                u64 av = a2[mp];
                acc2[mp][0] = f2fma(av, b0, acc2[mp][0]);
                acc2[mp][1] = f2fma(av, b1, acc2[mp][1]);
                acc2[mp][2] = f2fma(av, b2, acc2[mp][2]);
                acc2[mp][3] = f2fma(av, b3, acc2[mp][3]);
            }
        }
    }

    const int n = n0 + tx * 4;
    if (n < NG) {
        float4 blv = *(const float4*)(bl + n);
        #pragma unroll
        for (int mp = 0; mp < 4; mp++) {
            float x0,x1,y0,y1,z0,z1,q0,q1;
            f2unpack(acc2[mp][0], x0, x1);
            f2unpack(acc2[mp][1], y0, y1);
            f2unpack(acc2[mp][2], z0, z1);
            f2unpack(acc2[mp][3], q0, q1);
            int t = t0 + ty*8 + 2*mp;
            float4 o0 = make_float4(x0+blv.x, y0+blv.y, z0+blv.z, q0+blv.w);
            float4 o1 = make_float4(x1+blv.x, y1+blv.y, z1+blv.z, q1+blv.w);
            *(float4*)(g_xz + ((size_t)b*TT + t  )*NG + n) = o0;
            *(float4*)(g_xz + ((size_t)b*TT + t+1)*NG + n) = o1;
        }
    }
}

// ---------------------------------------------------------------------------
// persistent recurrence kernel v7: dual-group CTA with LENGTH-SORTED groups.
// grid = 152 CTAs (1/SM) x 512 threads. Block j: half0 (threads 0-255) runs
// group j (long), half1 runs group 15-j (short). Groups are 8 rows of the
// descending length-sorted permutation -> antipodal pairing balances per-SM
// work; the short half retires early and the long half gets the whole SM.
// Within a group rows are descending by length -> active rows at step t are
// the prefix [0, nact); frozen rows are skipped ENTIRELY (no carry: row b's
// final h lives in buffer lengths[b]&1, which final_kernel reads directly).
// Per half: warp w (0..7) owns units ua=u0+2w, ub=ua+1; lane = kc*4+gate;
// W in 40 u64 regs. Flag barrier per group (19 CTAs) as in r8-r10.
// ---------------------------------------------------------------------------
__global__ __launch_bounds__(512, 1) void lstm_persistent(
    const float* __restrict__ W,
    const int*   __restrict__ lengths)
{
    __shared__ __align__(16) float hs2[2][ROWSG*KPADF];
    __shared__ __align__(16) float zs2[2][ROWSG*64];
    __shared__ int prow2[2][ROWSG];
    __shared__ int sl2[2][ROWSG];

    const int tid  = threadIdx.x;
    const int half = tid >> 8;
    const int t256 = tid & 255;
    const int wid  = t256 >> 5;            // warp within half (0..7)
    const int lane = tid & 31;
    const int kc   = lane >> 2;            // k-chunk 0..7
    const int gg   = lane & 3;             // gate

    const int jblk  = blockIdx.x / NTIL;
    const int ntile = blockIdx.x % NTIL;
    const int gid   = half ? (NGRP - 1 - jblk) : jblk;
    const int u0    = ntile * UCTA;
    const int ua    = u0 + 2*wid;
    const int ub    = ua + 1;

    if (t256 < ROWSG) {
        int pr = g_perm[gid*ROWSG + t256];
        prow2[half][t256] = pr;
        sl2[half][t256]   = lengths[pr];
    }

    // W -> registers: 2 units x 20 f32x2 per thread (step-invariant)
    u64 w2a[20], w2b[20];
    #pragma unroll
    for (int i = 0; i < 20; i++) {
        int k0 = kc*KCH + 2*i;
        int k1 = k0 + 1;
        float a_lo = (k0 < HH && ua < HH) ? W[(size_t)(HH + k0)*NG + gg*HH + ua] : 0.f;
        float a_hi = (k1 < HH && ua < HH) ? W[(size_t)(HH + k1)*NG + gg*HH + ua] : 0.f;
        float b_lo = (k0 < HH && ub < HH) ? W[(size_t)(HH + k0)*NG + gg*HH + ub] : 0.f;
        float b_hi = (k1 < HH && ub < HH) ? W[(size_t)(HH + k1)*NG + gg*HH + ub] : 0.f;
        w2a[i] = f2pack(a_lo, a_hi);
        w2b[i] = f2pack(b_lo, b_hi);
    }
    __syncthreads();   // last whole-CTA sync (halves diverge after this)

    int sl[ROWSG];
    #pragma unroll
    for (int i = 0; i < ROWSG; i++) sl[i] = sl2[half][i];
    const int maxlen = sl[0];              // rows descending within group

    // epilogue mapping: first 128 threads of the half own one (row, unit)
    const bool e_has  = (t256 < ROWSG*UCTA);
    const int  e_mm   = (t256 >> 4) & 7;
    const int  e_uu   = t256 & 15;
    const int  e_u    = u0 + e_uu;
    const bool e_uval = e_has && (e_u < HH);
    const int  e_b    = prow2[half][e_mm];
    const int  e_len  = e_has ? sl[e_mm] : 0;

    float* hsh = hs2[half];
    float* zsh = zs2[half];
    int*   prw = prow2[half];
    int*   flagbase = &g_flag[gid*32];
    int*   myflag   = flagbase + ntile;

    float c_reg = 0.f;   // cell state for (e_b, e_u)

    for (int t = 0; t < maxlen; t++) {
        const float* hread  = g_h[t & 1];
        float*       hwrite = g_h[(t & 1) ^ 1];
        const bool   act    = e_uval && (t < e_len);

        // active prefix (uniform across half: sl identical in all its threads)
        int nact = 0;
        #pragma unroll
        for (int i = 0; i < ROWSG; i++) nact += (sl[i] > t);

        // prefetch xz (epilogue operands; latency hidden behind staging+matmul)
        const float* xzp = g_xz + ((size_t)e_b*TT + t)*NG + (e_uval ? e_u : 0);
        float pf0 = act ? __ldcg(xzp + 0*HH) : 0.f;
        float pf1 = act ? __ldcg(xzp + 1*HH) : 0.f;
        float pf2 = act ? __ldcg(xzp + 2*HH) : 0.f;
        float pf3 = act ? __ldcg(xzp + 3*HH) : 0.f;

        // stage ACTIVE h rows only: nact rows x 320 (chunks of 40, stride 44)
        {
            const int lim = nact * 80;
            #pragma unroll
            for (int s = 0; s < 3; s++) {
                int l = t256 + s*256;
                if (l < lim) {
                    int m  = l / 80;
                    int q  = l - m*80;
                    int kk = q / 10;
                    int ii = q - kk*10;
                    int k  = kk*KCH + ii*4;
                    float4 v = make_float4(0.f, 0.f, 0.f, 0.f);
                    if (k < HH)
                        v = __ldcg((const float4*)(hread + (size_t)prw[m]*HH + k));
                    *(float4*)&hsh[m*KPADF + kk*KST + ii*4] = v;
                }
            }
        }
        barh(half);

        // matmul over active rows: 2 unit dot-products per thread per row
        for (int m = 0; m < nact; m++) {
            const u64* h2 = (const u64*)(hsh + m*KPADF + kc*KST);
            u64 A0 = 0ull, A1 = 0ull, B0 = 0ull, B1 = 0ull;
            #pragma unroll
            for (int i = 0; i < 20; i += 2) {
                u64 ha = h2[i];
                u64 hb = h2[i+1];
                A0 = f2fma(w2a[i],   ha, A0);
                A1 = f2fma(w2a[i+1], hb, A1);
                B0 = f2fma(w2b[i],   ha, B0);
                B1 = f2fma(w2b[i+1], hb, B1);
            }
            float al, ah, bl_, bh;
            f2unpack(f2add(A0, A1), al, ah);
            f2unpack(f2add(B0, B1), bl_, bh);
            float va = al + ah;
            float vb = bl_ + bh;
            #pragma unroll
            for (int o = 4; o <= 16; o <<= 1) {
                va += __shfl_xor_sync(0xffffffffu, va, o);
                vb += __shfl_xor_sync(0xffffffffu, vb, o);
            }
            if (kc == 0) {
                zsh[m*64 + (2*wid + 0)*4 + gg] = va;
                zsh[m*64 + (2*wid + 1)*4 + gg] = vb;
            }
        }
        barh(half);

        // epilogue: one (row, unit) per thread; NO frozen-row carry
        if (act) {
            float4 zv = *(const float4*)&zsh[e_mm*64 + e_uu*4];
            float zi = zv.x + pf0;
            float zj = zv.y + pf1;
            float zf = zv.z + pf2;
            float zo = zv.w + pf3;
            float si = 1.f / (1.f + __expf(-zi));
            float sf = 1.f / (1.f + __expf(-(zf + 1.f)));  // FORGET_BIAS=1
            float so = 1.f / (1.f + __expf(-zo));
            float tj = tanhf(zj);
            c_reg = c_reg * sf + si * tj;
            float hnew = tanhf(c_reg) * so;
            __stcg(&hwrite[e_b*HH + e_u], hnew);
        }

        // group barrier: release -> flags -> acquire-poll
        barh(half);
        if (t256 == 0) {
            asm volatile("st.release.gpu.s32 [%0], %1;"
                         :: "l"(myflag), "r"(t + 1) : "memory");
        }
        if (t256 < 32) {
            const bool has = (lane < NTIL);
            int* pp = flagbase + (has ? lane : 0);
            const int target = t + 1;
            int v;
            do {
                asm volatile("ld.acquire.gpu.s32 %0, [%1];"
                             : "=r"(v) : "l"(pp) : "memory");
            } while (!__all_sync(0xffffffffu, !has || (v >= target)));
        }
        barh(half);
    }
}

// ---------------------------------------------------------------------------
// final: logits + mean NLL. Row b's final h lives in buffer (lengths[b] & 1):
// its last write was at t = len-1 into buffer ((len-1)&1)^1 = len&1.
// ---------------------------------------------------------------------------
__global__ void final_kernel(
    const float* __restrict__ Wd,
    const float* __restrict__ bd,
    const int*   __restrict__ labels,
    const int*   __restrict__ lengths,
    float*       __restrict__ out,
    int out_size)
{
    __shared__ float red[128];
    __shared__ float wd_s[900];
    int b = threadIdx.x;
    for (int i = b; i < 900; i += 128) wd_s[i] = Wd[i];
    __syncthreads();

    const float* h = g_h[lengths[b] & 1] + b*HH;

    float a0 = bd[0], a1 = bd[1], a2 = bd[2];
    #pragma unroll 5
    for (int k = 0; k < HH; k += 4) {
        float4 hv = *(const float4*)(h + k);
        a0 += hv.x*wd_s[(k+0)*3+0] + hv.y*wd_s[(k+1)*3+0]
            + hv.z*wd_s[(k+2)*3+0] + hv.w*wd_s[(k+3)*3+0];
        a1 += hv.x*wd_s[(k+0)*3+1] + hv.y*wd_s[(k+1)*3+1]
            + hv.z*wd_s[(k+2)*3+1] + hv.w*wd_s[(k+3)*3+1];
        a2 += hv.x*wd_s[(k+0)*3+2] + hv.y*wd_s[(k+1)*3+2]
            + hv.z*wd_s[(k+2)*3+2] + hv.w*wd_s[(k+3)*3+2];
    }
    float mx  = fmaxf(a0, fmaxf(a1, a2));
    float lse = mx + logf(expf(a0 - mx) + expf(a1 - mx) + expf(a2 - mx));
    int   lab = labels[b];
    float sel = (lab == 0) ? a0 : ((lab == 1) ? a1 : a2);
    float nll = lse - sel;

    int off = (out_size >= 385) ? 1 : 0;
    if (out_size >= 384) {
        out[off + b*3 + 0] = a0;
        out[off + b*3 + 1] = a1;
        out[off + b*3 + 2] = a2;
    }
    red[b] = nll;
    __syncthreads();
    for (int s = 64; s; s >>= 1) {
        if (b < s) red[b] += red[b + s];
        __syncthreads();
    }
    if (b == 0 && (off == 1 || out_size < 384)) out[0] = red[0] * (1.f / 128.f);
}

// ---------------------------------------------------------------------------
extern "C" void kernel_launch(void* const* d_in, const int* in_sizes, int n_in,
                              void* d_out, int out_size)
{
    const int*   ids     = (const int*)  d_in[0];
    const int*   lengths = (const int*)  d_in[1];
    const int*   labels  = (const int*)  d_in[2];
    const float* emb     = (const float*)d_in[3];
    const float* W       = (const float*)d_in[4];
    const float* bl      = (const float*)d_in[5];
    const float* Wd      = (const float*)d_in[6];
    const float* bd      = (const float*)d_in[7];
    float* out = (float*)d_out;

    init_kernel<<<(BB*HH + 255)/256, 256>>>(lengths);
    precompute_kernel<<<dim3(19, 4, BB), 256>>>(ids, lengths, emb, W, bl);
    lstm_persistent<<<NCTAS, 512>>>(W, lengths);
    final_kernel<<<1, 128>>>(Wd, bd, labels, lengths, out, out_size);
}

// round 13
// speedup vs baseline: 1.4801x; 1.2840x over previous
#include <cuda_runtime.h>
#include <math.h>

#define BB 128
#define TT 512
#define DD 300
#define HH 300
#define NG 1200      // 4*H
#define NGRP 16      // groups of 8 rows; one 8-CTA cluster per group
#define ROWSG 8
#define CL 8         // cluster size (portable max)
#define UPC 38       // units per CTA (8*38 = 304 >= 300)
#define KC2 38       // k per chunk
#define KSTW 42      // chunk stride in floats (banks 10*kc mod 32 distinct)
#define HROW (8*KSTW)   // 336 floats per h row
#define HBUF (ROWSG*HROW)          // floats per parity
#define NCTAS (NGRP*CL) // 128 CTAs

typedef unsigned long long u64;

// ---- packed f32x2 helpers (FFMA2: only reachable via PTX) ----
__device__ __forceinline__ u64 f2pack(float lo, float hi) {
    u64 d; asm("mov.b64 %0, {%1, %2};" : "=l"(d) : "f"(lo), "f"(hi)); return d;
}
__device__ __forceinline__ void f2unpack(u64 v, float& lo, float& hi) {
    asm("mov.b64 {%0, %1}, %2;" : "=f"(lo), "=f"(hi) : "l"(v));
}
__device__ __forceinline__ u64 f2fma(u64 a, u64 b, u64 c) {
    u64 d; asm("fma.rn.f32x2 %0, %1, %2, %3;" : "=l"(d) : "l"(a), "l"(b), "l"(c)); return d;
}

__device__ __forceinline__ unsigned smem_u32(const void* p) {
    unsigned a;
    asm("{ .reg .u64 t; cvta.to.shared.u64 t, %1; cvt.u32.u64 %0, t; }" : "=r"(a) : "l"(p));
    return a;
}

// ---- device scratch ----
__device__ float g_h[2][BB*HH];          // final-h handoff (parity len&1)
__device__ float g_xz[(size_t)BB*TT*NG]; // precomputed x@Wx + b_lstm
__device__ int   g_perm[BB];             // rows sorted by length descending

// ---------------------------------------------------------------------------
__global__ void init_kernel(const int* __restrict__ lengths) {
    int i = blockIdx.x * blockDim.x + threadIdx.x;
    if (i < BB*HH) { g_h[0][i] = 0.f; g_h[1][i] = 0.f; }
    __shared__ int sle[BB];
    if (blockIdx.x == 0) {
        if (threadIdx.x < BB) sle[threadIdx.x] = lengths[threadIdx.x];
        __syncthreads();
        if (threadIdx.x < BB) {
            int t  = threadIdx.x;
            int me = sle[t];
            int rank = 0;
            for (int j = 0; j < BB; j++)
                rank += (sle[j] > me) || (sle[j] == me && j < t);
            g_perm[rank] = t;
        }
    }
}

// ---------------------------------------------------------------------------
// precompute (FFMA2 version, unchanged from passing rounds 7-11)
// ---------------------------------------------------------------------------
__global__ __launch_bounds__(256) void precompute_kernel(
    const int*   __restrict__ ids,
    const int*   __restrict__ lengths,
    const float* __restrict__ emb,
    const float* __restrict__ W,
    const float* __restrict__ bl)
{
    const int b  = blockIdx.z;
    const int t0 = blockIdx.y * 128;
    const int n0 = blockIdx.x * 64;
    if (lengths[b] <= t0) return;

    __shared__ float As[16][128];
    __shared__ float Bs[16][64];
    __shared__ int   toks[128];

    const int tid = threadIdx.x;
    if (tid < 128) toks[tid] = ids[b*TT + t0 + tid];

    const int tx = tid & 15;
    const int ty = tid >> 4;
    u64 acc2[4][4];
    #pragma unroll
    for (int i = 0; i < 4; i++)
        #pragma unroll
        for (int j = 0; j < 4; j++) acc2[i][j] = 0ull;

    for (int k0 = 0; k0 < 300; k0 += 16) {
        __syncthreads();
        for (int l = tid; l < 512; l += 256) {
            int r  = l >> 2;
            int kq = l & 3;
            int k  = k0 + kq * 4;
            float4 v = make_float4(0.f, 0.f, 0.f, 0.f);
            if (k < 300) v = *(const float4*)(emb + (size_t)toks[r]*DD + k);
            As[kq*4+0][r] = v.x;
            As[kq*4+1][r] = v.y;
            As[kq*4+2][r] = v.z;
            As[kq*4+3][r] = v.w;
        }
        {
            int l  = tid;
            int kk = l >> 4;
            int q  = l & 15;
            int k  = k0 + kk;
            int n  = n0 + q * 4;
            float4 v = make_float4(0.f, 0.f, 0.f, 0.f);
            if (k < 300 && n < NG) v = *(const float4*)(W + (size_t)k*NG + n);
            *(float4*)&Bs[kk][q*4] = v;
        }
        __syncthreads();
        #pragma unroll
        for (int kk = 0; kk < 16; kk++) {
            float4 bv = *(const float4*)&Bs[kk][tx*4];
            u64 b0 = f2pack(bv.x, bv.x);
            u64 b1 = f2pack(bv.y, bv.y);
            u64 b2 = f2pack(bv.z, bv.z);
            u64 b3 = f2pack(bv.w, bv.w);
            const u64* a2 = (const u64*)&As[kk][ty*8];
            #pragma unroll
            for (int mp = 0; mp < 4; mp++) {
                u64 av = a2[mp];
                acc2[mp][0] = f2fma(av, b0, acc2[mp][0]);
                acc2[mp][1] = f2fma(av, b1, acc2[mp][1]);
                acc2[mp][2] = f2fma(av, b2, acc2[mp][2]);
                acc2[mp][3] = f2fma(av, b3, acc2[mp][3]);
            }
        }
    }

    const int n = n0 + tx * 4;
    if (n < NG) {
        float4 blv = *(const float4*)(bl + n);
        #pragma unroll
        for (int mp = 0; mp < 4; mp++) {
            float x0,x1,y0,y1,z0,z1,q0,q1;
            f2unpack(acc2[mp][0], x0, x1);
            f2unpack(acc2[mp][1], y0, y1);
            f2unpack(acc2[mp][2], z0, z1);
            f2unpack(acc2[mp][3], q0, q1);
            int t = t0 + ty*8 + 2*mp;
            float4 o0 = make_float4(x0+blv.x, y0+blv.y, z0+blv.z, q0+blv.w);
            float4 o1 = make_float4(x1+blv.x, y1+blv.y, z1+blv.z, q1+blv.w);
            *(float4*)(g_xz + ((size_t)b*TT + t  )*NG + n) = o0;
            *(float4*)(g_xz + ((size_t)b*TT + t+1)*NG + n) = o1;
        }
    }
}

// ---------------------------------------------------------------------------
// persistent recurrence v8: 8-CTA CLUSTER per group, DSMEM h exchange.
// Each CTA: full local copy of group h (parity double-buffered smem), owns
// 38 units. Step: matmul (local smem) -> epilogue -> push h pairs into all
// 8 CTAs' smem (mapa + st.shared::cluster.b64) -> barrier.cluster (release/
// acquire orders pushes). No flags, no L2 h traffic, no staging.
// Rows sorted desc in group -> active prefix; frozen rows never read.
// g_h written per active step so final reads parity lengths[b]&1.
// ---------------------------------------------------------------------------
__global__ __launch_bounds__(256, 1) __cluster_dims__(CL, 1, 1)
void lstm_persistent(
    const float* __restrict__ W,
    const int*   __restrict__ lengths)
{
    __shared__ __align__(16) float hsm[2][HBUF];   // 2 x 8 x 336
    __shared__ __align__(16) float zsm[ROWSG*160]; // 8 rows x 40 slots x 4 gates
    __shared__ int sli[ROWSG], spr[ROWSG];

    const int tid   = threadIdx.x;
    const int wid   = tid >> 5;
    const int lane  = tid & 31;
    const int kc    = lane >> 2;          // k-chunk 0..7
    const int gg    = lane & 3;           // gate
    const int gid   = blockIdx.x / CL;
    const int crank = blockIdx.x % CL;

    if (tid < ROWSG) {
        int pr = g_perm[gid*ROWSG + tid];
        spr[tid] = pr;
        sli[tid] = lengths[pr];
    }
    // zero both hsm parities (pad slots stay 0 forever)
    {
        float4 z4 = make_float4(0.f, 0.f, 0.f, 0.f);
        float4* p4 = (float4*)&hsm[0][0];
        for (int l = tid; l < 2*HBUF/4; l += 256) p4[l] = z4;
    }

    // W -> registers: 5 unit-slots x 19 f32x2 (this thread's k-chunk, gate)
    u64 w2[5][19];
    #pragma unroll
    for (int jj = 0; jj < 5; jj++) {
        int  ul = wid*5 + jj;
        int  ug = crank*UPC + ul;
        bool uv = (ul < UPC) && (ug < HH);
        int  col = gg*HH + (uv ? ug : 0);
        #pragma unroll
        for (int i = 0; i < 19; i++) {
            int k0 = kc*KC2 + 2*i;
            float lo = (uv && k0     < HH) ? W[(size_t)(HH + k0    )*NG + col] : 0.f;
            float hi = (uv && k0 + 1 < HH) ? W[(size_t)(HH + k0 + 1)*NG + col] : 0.f;
            w2[jj][i] = f2pack(lo, hi);
        }
    }
    __syncthreads();
    int slr[ROWSG];
    #pragma unroll
    for (int i = 0; i < ROWSG; i++) slr[i] = sli[i];
    const int maxlen = slr[0];

    // epilogue mapping: tid<152 owns (row m, unit pair ul2, ul2+1)
    const bool e_has = (tid < ROWSG*19);
    const int  e_m   = e_has ? tid/19 : 0;
    const int  e_jp  = e_has ? tid - e_m*19 : 0;
    const int  e_ul  = 2*e_jp;
    const int  e_ug  = crank*UPC + e_ul;
    const bool e_val = e_has && (e_ug < HH);   // pairs fully valid/invalid
    const int  e_b   = spr[e_m];
    const int  e_len = e_has ? slr[e_m] : 0;
    const unsigned e_offb = (unsigned)((e_m*HROW + crank*KSTW + e_ul) * 4);

    // mapa'd peer base addresses for hsm[0]
    unsigned rbase[CL];
    {
        unsigned locb = smem_u32(&hsm[0][0]);
        #pragma unroll
        for (int r = 0; r < CL; r++)
            asm("mapa.shared::cluster.u32 %0, %1, %2;"
                : "=r"(rbase[r]) : "r"(locb), "r"(r));
    }

    // all CTAs' hsm zero before any pushes can land
    asm volatile("barrier.cluster.arrive.aligned;" ::: "memory");
    asm volatile("barrier.cluster.wait.aligned;"   ::: "memory");

    float c0 = 0.f, c1 = 0.f;

    for (int t = 0; t < maxlen; t++) {
        const int p = t & 1;
        const unsigned poff = (unsigned)(p ^ 1) * (unsigned)(HBUF * 4);
        float* hwr = g_h[p ^ 1];
        int nact = 0;
        #pragma unroll
        for (int i = 0; i < ROWSG; i++) nact += (slr[i] > t);
        const bool act = e_val && (t < e_len);

        // prefetch xz for the epilogue pair (hidden behind matmul)
        float pf[4][2];
        {
            const float* xp = g_xz + ((size_t)e_b*TT + t)*NG + (e_val ? e_ug : 0);
            #pragma unroll
            for (int g = 0; g < 4; g++) {
                pf[g][0] = act ? __ldcg(xp + g*HH    ) : 0.f;
                pf[g][1] = act ? __ldcg(xp + g*HH + 1) : 0.f;
            }
        }

        // matmul over active rows (h entirely in LOCAL smem)
        const float* hp = &hsm[p][0];
        for (int m = 0; m < nact; m++) {
            const u64* h2 = (const u64*)(hp + m*HROW + kc*KSTW);
            u64 A0=0ull, A1=0ull, A2=0ull, A3=0ull, A4=0ull;
            #pragma unroll
            for (int i = 0; i < 19; i++) {
                u64 hv = h2[i];
                A0 = f2fma(w2[0][i], hv, A0);
                A1 = f2fma(w2[1][i], hv, A1);
                A2 = f2fma(w2[2][i], hv, A2);
                A3 = f2fma(w2[3][i], hv, A3);
                A4 = f2fma(w2[4][i], hv, A4);
            }
            float v0,v1,v2,v3,v4,lo,hi;
            f2unpack(A0, lo, hi); v0 = lo + hi;
            f2unpack(A1, lo, hi); v1 = lo + hi;
            f2unpack(A2, lo, hi); v2 = lo + hi;
            f2unpack(A3, lo, hi); v3 = lo + hi;
            f2unpack(A4, lo, hi); v4 = lo + hi;
            #pragma unroll
            for (int o = 4; o <= 16; o <<= 1) {
                v0 += __shfl_xor_sync(0xffffffffu, v0, o);
                v1 += __shfl_xor_sync(0xffffffffu, v1, o);
                v2 += __shfl_xor_sync(0xffffffffu, v2, o);
                v3 += __shfl_xor_sync(0xffffffffu, v3, o);
                v4 += __shfl_xor_sync(0xffffffffu, v4, o);
            }
            if (lane < 4) {   // kc == 0; gg = lane
                float* zb = &zsm[m*160 + wid*20 + gg];
                zb[ 0] = v0;
                zb[ 4] = v1;
                zb[ 8] = v2;
                zb[12] = v3;
                zb[16] = v4;
            }
        }
        __syncthreads();

        // epilogue: 2 units per thread; push h pair to all 8 CTAs' smem
        if (act) {
            float4 za = *(const float4*)&zsm[e_m*160 + e_ul*4];
            float4 zb = *(const float4*)&zsm[e_m*160 + e_ul*4 + 4];
            // unit e_ug
            float zi = za.x + pf[0][0];
            float zj = za.y + pf[1][0];
            float zf = za.z + pf[2][0];
            float zo = za.w + pf[3][0];
            float si = 1.f / (1.f + __expf(-zi));
            float sf = 1.f / (1.f + __expf(-(zf + 1.f)));  // FORGET_BIAS=1
            float so = 1.f / (1.f + __expf(-zo));
            float tj = tanhf(zj);
            c0 = c0 * sf + si * tj;
            float h0 = tanhf(c0) * so;
            // unit e_ug+1
            zi = zb.x + pf[0][1];
            zj = zb.y + pf[1][1];
            zf = zb.z + pf[2][1];
            zo = zb.w + pf[3][1];
            si = 1.f / (1.f + __expf(-zi));
            sf = 1.f / (1.f + __expf(-(zf + 1.f)));
            so = 1.f / (1.f + __expf(-zo));
            tj = tanhf(zj);
            c1 = c1 * sf + si * tj;
            float h1 = tanhf(c1) * so;

            __stcg(&hwr[e_b*HH + e_ug],     h0);
            __stcg(&hwr[e_b*HH + e_ug + 1], h1);

            u64 hv2 = f2pack(h0, h1);
            unsigned off = poff + e_offb;
            #pragma unroll
            for (int r = 0; r < CL; r++)
                asm volatile("st.shared::cluster.b64 [%0], %1;"
                             :: "r"(rbase[r] + off), "l"(hv2) : "memory");
        }

        // cluster barrier: release pushes -> all CTAs see new h
        asm volatile("barrier.cluster.arrive.aligned;" ::: "memory");
        asm volatile("barrier.cluster.wait.aligned;"   ::: "memory");
    }
}

// ---------------------------------------------------------------------------
// final: logits + mean NLL. Row b's final h lives in buffer (lengths[b] & 1).
// ---------------------------------------------------------------------------
__global__ void final_kernel(
    const float* __restrict__ Wd,
    const float* __restrict__ bd,
    const int*   __restrict__ labels,
    const int*   __restrict__ lengths,
    float*       __restrict__ out,
    int out_size)
{
    __shared__ float red[128];
    __shared__ float wd_s[900];
    int b = threadIdx.x;
    for (int i = b; i < 900; i += 128) wd_s[i] = Wd[i];
    __syncthreads();

    const float* h = g_h[lengths[b] & 1] + b*HH;

    float a0 = bd[0], a1 = bd[1], a2 = bd[2];
    #pragma unroll 5
    for (int k = 0; k < HH; k += 4) {
        float4 hv = *(const float4*)(h + k);
        a0 += hv.x*wd_s[(k+0)*3+0] + hv.y*wd_s[(k+1)*3+0]
            + hv.z*wd_s[(k+2)*3+0] + hv.w*wd_s[(k+3)*3+0];
        a1 += hv.x*wd_s[(k+0)*3+1] + hv.y*wd_s[(k+1)*3+1]
            + hv.z*wd_s[(k+2)*3+1] + hv.w*wd_s[(k+3)*3+1];
        a2 += hv.x*wd_s[(k+0)*3+2] + hv.y*wd_s[(k+1)*3+2]
            + hv.z*wd_s[(k+2)*3+2] + hv.w*wd_s[(k+3)*3+2];
    }
    float mx  = fmaxf(a0, fmaxf(a1, a2));
    float lse = mx + logf(expf(a0 - mx) + expf(a1 - mx) + expf(a2 - mx));
    int   lab = labels[b];
    float sel = (lab == 0) ? a0 : ((lab == 1) ? a1 : a2);
    float nll = lse - sel;

    int off = (out_size >= 385) ? 1 : 0;
    if (out_size >= 384) {
        out[off + b*3 + 0] = a0;
        out[off + b*3 + 1] = a1;
        out[off + b*3 + 2] = a2;
    }
    red[b] = nll;
    __syncthreads();
    for (int s = 64; s; s >>= 1) {
        if (b < s) red[b] += red[b + s];
        __syncthreads();
    }
    if (b == 0 && (off == 1 || out_size < 384)) out[0] = red[0] * (1.f / 128.f);
}

// ---------------------------------------------------------------------------
extern "C" void kernel_launch(void* const* d_in, const int* in_sizes, int n_in,
                              void* d_out, int out_size)
{
    const int*   ids     = (const int*)  d_in[0];
    const int*   lengths = (const int*)  d_in[1];
    const int*   labels  = (const int*)  d_in[2];
    const float* emb     = (const float*)d_in[3];
    const float* W       = (const float*)d_in[4];
    const float* bl      = (const float*)d_in[5];
    const float* Wd      = (const float*)d_in[6];
    const float* bd      = (const float*)d_in[7];
    float* out = (float*)d_out;

    init_kernel<<<(BB*HH + 255)/256, 256>>>(lengths);
    precompute_kernel<<<dim3(19, 4, BB), 256>>>(ids, lengths, emb, W, bl);
    lstm_persistent<<<NCTAS, 256>>>(W, lengths);
    final_kernel<<<1, 128>>>(Wd, bd, labels, lengths, out, out_size);
}